// round 15
// baseline (speedup 1.0000x reference)
#include <cuda_runtime.h>
#include <math.h>
#include <stdint.h>

// Problem constants
#define BT_    16
#define NH_    8
#define HD_    64
#define SEQ_   1024
#define NTOK_  16384
#define DIM_   512
#define INNER_ 512
#define QKVN_  1536
#define GK_    512

#define PI_F 3.14159265358979323846f
#define LOG2E_F 1.4426950408889634f

// GEMM tiling: 128x128 tile, K-chunk 32, 3-stage cp.async pipeline, 2 CTA/SM
#define GSTRIDE 36
#define STAGE_FLOATS (2 * 128 * GSTRIDE)
#define STAGE_BYTES  (STAGE_FLOATS * 4)
#define GSTAGES 3
#define GEMM_SMEM_BYTES (GSTAGES * STAGE_BYTES)    // 110592

// Attention smem: BQ=128. sQ[128][68] + 2 x (sK[32][68] + sV[32][68]) -> 3 CTA/SM
#define AQS_ 68
#define A_SQ_OFF   0
#define A_KV_OFF   (128 * AQS_)
#define KVBUF_UINTS (2 * 32 * AQS_)
#define ATTN_SMEM_UINTS (A_KV_OFF + 2 * KVBUF_UINTS)
#define ATTN_SMEM_BYTES (ATTN_SMEM_UINTS * 4)      // 69632

// Scratch
__device__ float g_qkv[(size_t)NTOK_ * QKVN_];
__device__ float g_attn[(size_t)NTOK_ * INNER_];
__device__ float g_x[(size_t)NTOK_ * DIM_];
__device__ float g_wq[(size_t)QKVN_ * DIM_];
__device__ float g_wo[(size_t)INNER_ * DIM_];
__device__ float2 g_rope[32 * 32];                 // [pos][pair] -> (cos, sin)

// ---------------------------------------------------------------------------
__device__ __forceinline__ uint32_t f2tf32(float x) {
    uint32_t r;
    asm("cvt.rna.tf32.f32 %0, %1;" : "=r"(r) : "f"(x));
    return r;
}
__device__ __forceinline__ float tf32r(float x) { return __uint_as_float(f2tf32(x)); }
__device__ __forceinline__ uint32_t smem_u32(const void* p) {
    uint32_t a;
    asm("{ .reg .u64 t; cvta.to.shared.u64 t, %1; cvt.u32.u64 %0, t; }"
        : "=r"(a) : "l"(p));
    return a;
}
__device__ __forceinline__ void cp16(uint32_t saddr, const void* gaddr) {
    asm volatile("cp.async.cg.shared.global [%0], [%1], 16;"
                 :: "r"(saddr), "l"(gaddr) : "memory");
}
#define CP_COMMIT() asm volatile("cp.async.commit_group;" ::: "memory")
#define CP_WAIT1()  asm volatile("cp.async.wait_group 1;" ::: "memory")
#define CP_WAIT0()  asm volatile("cp.async.wait_group 0;" ::: "memory")

#define MMA_TF32(c0, c1, c2, c3, a0, a1, a2, a3, b0, b1) \
    asm volatile("mma.sync.aligned.m16n8k8.row.col.f32.tf32.tf32.f32 " \
        "{%0,%1,%2,%3}, {%4,%5,%6,%7}, {%8,%9}, {%0,%1,%2,%3};" \
        : "+f"(c0), "+f"(c1), "+f"(c2), "+f"(c3) \
        : "r"(a0), "r"(a1), "r"(a2), "r"(a3), "r"(b0), "r"(b1))

// ---------------------------------------------------------------------------
// Fused prologue: tf32-round x, w_qkv, w_out + build rope table, one launch.
// ---------------------------------------------------------------------------
#define N4X (NTOK_ * DIM_ / 4)
#define N4Q (QKVN_ * DIM_ / 4)
#define N4O (INNER_ * DIM_ / 4)

__global__ __launch_bounds__(256) void prologue_kernel(
    const float* __restrict__ x,  float* __restrict__ xr,
    const float* __restrict__ wq, float* __restrict__ wqr,
    const float* __restrict__ wo, float* __restrict__ wor,
    float2* __restrict__ tab)
{
    int i = blockIdx.x * blockDim.x + threadIdx.x;
    if (i < 1024) {
        int pidx = i >> 5;
        int p = i & 31;
        float base = (1.0f + (float)(p & 15) * (127.0f / 15.0f)) * PI_F;
        float pos = -1.0f + (float)pidx * (2.0f / 31.0f);
        float s, c;
        sincosf(pos * base, &s, &c);
        tab[i] = make_float2(c, s);
    }
    const float* src; float* dst; int idx;
    if (i < N4X)                 { src = x;  dst = xr;  idx = i; }
    else if (i < N4X + N4Q)      { src = wq; dst = wqr; idx = i - N4X; }
    else if (i < N4X + N4Q + N4O){ src = wo; dst = wor; idx = i - N4X - N4Q; }
    else return;
    float4 v = reinterpret_cast<const float4*>(src)[idx];
    uint4 u = make_uint4(f2tf32(v.x), f2tf32(v.y), f2tf32(v.z), f2tf32(v.w));
    reinterpret_cast<uint4*>(dst)[idx] = u;
}

// ---------------------------------------------------------------------------
// tf32 mma.sync GEMM, 3-stage cp.async pipeline, 2 CTAs/SM.
// Single barrier per K-iteration (top barrier orders prior compute vs refill).
// mode 0: C = A*B^T + bias. mode 1: fused RoPE on q,k cols + tf32 round k,v.
// ---------------------------------------------------------------------------
__global__ __launch_bounds__(256, 2) void gemm_mma(
    const float* __restrict__ A, const float* __restrict__ B,
    const float* __restrict__ bias, float* __restrict__ C, int N,
    const float2* __restrict__ rope_tab, int mode)
{
    extern __shared__ float smem[];
    const uint32_t sbase = smem_u32(smem);

    const int tid = threadIdx.x;
    const int wid = tid >> 5;
    const int lane = tid & 31;
    const int g = lane >> 2;
    const int t = lane & 3;
    const int bm = blockIdx.y * 128;
    const int bn = blockIdx.x * 128;
    const int mbase = (wid >> 2) * 64;
    const int nbase = (wid & 3) * 32;

    auto issue = [&](int stage, int k0) {
        uint32_t sA = sbase + (uint32_t)stage * STAGE_BYTES;
        uint32_t sB = sA + 128 * GSTRIDE * 4;
#pragma unroll
        for (int it = 0; it < 4; it++) {
            int idx = tid + it * 256;
            int row = idx >> 3;
            int seg = (idx & 7) << 2;
            uint32_t so = (uint32_t)(row * (GSTRIDE * 4) + seg * 4);
            cp16(sA + so, &A[(size_t)(bm + row) * GK_ + k0 + seg]);
            cp16(sB + so, &B[(size_t)(bn + row) * GK_ + k0 + seg]);
        }
    };

    float C0[4][4][4];
#pragma unroll
    for (int mt = 0; mt < 4; mt++)
#pragma unroll
        for (int nt = 0; nt < 4; nt++)
#pragma unroll
            for (int f = 0; f < 4; f++) C0[mt][nt][f] = 0.0f;

    issue(0, 0);  CP_COMMIT();
    issue(1, 32); CP_COMMIT();

    for (int kt = 0; kt < 16; kt++) {
        CP_WAIT1();
        __syncthreads();   // orders: (a) chunk kt data visible to all,
                           // (b) prior compute on stage (kt+2)%3 done before refill

        if (kt + 2 < 16) issue((kt + 2) % GSTAGES, (kt + 2) * 32);
        CP_COMMIT();

        const int buf = kt % GSTAGES;
        const uint32_t* As = reinterpret_cast<const uint32_t*>(smem) + buf * STAGE_FLOATS;
        const uint32_t* Bs = As + 128 * GSTRIDE;

#pragma unroll
        for (int half = 0; half < 2; half++) {
            uint4 av[4][2];
            uint4 bv[4];
#pragma unroll
            for (int mt = 0; mt < 4; mt++) {
                int r0 = mbase + mt * 16 + g;
                av[mt][0] = *reinterpret_cast<const uint4*>(&As[r0 * GSTRIDE + 8 * t + 4 * half]);
                av[mt][1] = *reinterpret_cast<const uint4*>(&As[(r0 + 8) * GSTRIDE + 8 * t + 4 * half]);
            }
#pragma unroll
            for (int nt = 0; nt < 4; nt++) {
                int rn = nbase + nt * 8 + g;
                bv[nt] = *reinterpret_cast<const uint4*>(&Bs[rn * GSTRIDE + 8 * t + 4 * half]);
            }
#pragma unroll
            for (int ss = 0; ss < 2; ss++) {
#pragma unroll
                for (int mt = 0; mt < 4; mt++) {
                    uint32_t a0 = (ss == 0) ? av[mt][0].x : av[mt][0].z;
                    uint32_t a2 = (ss == 0) ? av[mt][0].y : av[mt][0].w;
                    uint32_t a1 = (ss == 0) ? av[mt][1].x : av[mt][1].z;
                    uint32_t a3 = (ss == 0) ? av[mt][1].y : av[mt][1].w;
#pragma unroll
                    for (int nt = 0; nt < 4; nt++) {
                        uint32_t b0 = (ss == 0) ? bv[nt].x : bv[nt].z;
                        uint32_t b1 = (ss == 0) ? bv[nt].y : bv[nt].w;
                        MMA_TF32(C0[mt][nt][0], C0[mt][nt][1], C0[mt][nt][2], C0[mt][nt][3],
                                 a0, a1, a2, a3, b0, b1);
                    }
                }
            }
        }
        // no trailing barrier: next iteration's top barrier provides ordering
    }

    // ---- Epilogue ----
#pragma unroll
    for (int mt = 0; mt < 4; mt++) {
        int row0 = bm + mbase + mt * 16 + g;
#pragma unroll
        for (int nt = 0; nt < 4; nt++) {
            int col = bn + nbase + nt * 8 + 2 * t;
            float v00 = C0[mt][nt][0], v01 = C0[mt][nt][1];
            float v10 = C0[mt][nt][2], v11 = C0[mt][nt][3];
            if (mode == 0) {
                float bx = 0.f, by = 0.f;
                if (bias) { bx = bias[col]; by = bias[col + 1]; }
                v00 += bx; v01 += by; v10 += bx; v11 += by;
            } else {
                if (col < 1024) {
                    int p = (col >> 1) & 31;
                    int pidx0 = (p < 16) ? ((row0 >> 5) & 31) : (row0 & 31);
                    int pidx1 = (p < 16) ? (((row0 + 8) >> 5) & 31) : ((row0 + 8) & 31);
                    float2 cs0 = rope_tab[(pidx0 << 5) | p];
                    float2 cs1 = rope_tab[(pidx1 << 5) | p];
                    float r00 = v00 * cs0.x - v01 * cs0.y;
                    float r01 = v01 * cs0.x + v00 * cs0.y;
                    float r10 = v10 * cs1.x - v11 * cs1.y;
                    float r11 = v11 * cs1.x + v10 * cs1.y;
                    if (col >= 512) {
                        r00 = tf32r(r00); r01 = tf32r(r01);
                        r10 = tf32r(r10); r11 = tf32r(r11);
                    }
                    v00 = r00; v01 = r01; v10 = r10; v11 = r11;
                } else {
                    v00 = tf32r(v00); v01 = tf32r(v01);
                    v10 = tf32r(v10); v11 = tf32r(v11);
                }
            }
            *reinterpret_cast<float2*>(&C[(size_t)row0 * N + col]) = make_float2(v00, v01);
            *reinterpret_cast<float2*>(&C[(size_t)(row0 + 8) * N + col]) = make_float2(v10, v11);
        }
    }
}

// ---------------------------------------------------------------------------
// Flash attention, tf32 mma.sync. 128 threads (4 warps x 32 q-rows),
// BK=32 KV tiles, cp.async double-buffered, row-major sV, register-P trick,
// 3 CTAs/SM. (Exact R12 configuration — best measured.)
// ---------------------------------------------------------------------------
__global__ __launch_bounds__(128, 3) void attn_mma(
    const float* __restrict__ qkv, float* __restrict__ outb)
{
    extern __shared__ uint32_t asm_[];
    uint32_t* sQ = asm_ + A_SQ_OFF;     // [128][68] tf32 (scaled)
    const uint32_t sbase = smem_u32(asm_);

    const int bh = blockIdx.y;
    const int bt = bh >> 3;
    const int h  = bh & 7;
    const int q0 = blockIdx.x * 128;
    const int tid = threadIdx.x;
    const int wid = tid >> 5;           // 0..3
    const int lane = tid & 31;
    const int g = lane >> 2;
    const int t = lane & 3;
    const int wq0 = wid * 32;

    const float qscale = 0.125f * LOG2E_F;

    // ---- Q -> sQ (scaled tf32) ----
    const size_t baseQ = ((size_t)bt * SEQ_ + q0) * QKVN_ + (size_t)h * HD_;
#pragma unroll
    for (int it = 0; it < 16; it++) {
        int idx = tid + it * 128;
        int r  = idx >> 4;
        int c4 = (idx & 15) << 2;
        float4 v = *reinterpret_cast<const float4*>(&qkv[baseQ + (size_t)r * QKVN_ + c4]);
        uint4 u = make_uint4(f2tf32(v.x * qscale), f2tf32(v.y * qscale),
                             f2tf32(v.z * qscale), f2tf32(v.w * qscale));
        *reinterpret_cast<uint4*>(&sQ[r * AQS_ + c4]) = u;
    }

    const size_t baseKV0 = (size_t)bt * SEQ_ * QKVN_ + 512 + (size_t)h * HD_;
    const int ldr = tid >> 4;               // 0..7
    const int ldc4 = (tid & 15) << 2;

    auto fill = [&](int kt, int buf) {
        const float* pK = &qkv[baseKV0 + (size_t)(kt * 32) * QKVN_];
        const float* pV = pK + 512;
        uint32_t ko = (uint32_t)(A_KV_OFF + buf * KVBUF_UINTS);
        uint32_t vo = ko + 32 * AQS_;
#pragma unroll
        for (int it = 0; it < 4; it++) {
            int r = ldr + it * 8;           // 0..31
            cp16(sbase + (ko + r * AQS_ + ldc4) * 4, &pK[(size_t)r * QKVN_ + ldc4]);
            cp16(sbase + (vo + r * AQS_ + ldc4) * 4, &pV[(size_t)r * QKVN_ + ldc4]);
        }
    };

    float O[2][8][4];
    float m_[2][2], l_[2][2];
#pragma unroll
    for (int mt = 0; mt < 2; mt++) {
#pragma unroll
        for (int r = 0; r < 2; r++) { m_[mt][r] = -1e30f; l_[mt][r] = 0.0f; }
#pragma unroll
        for (int nd = 0; nd < 8; nd++)
#pragma unroll
            for (int f = 0; f < 4; f++) O[mt][nd][f] = 0.0f;
    }

    fill(0, 0);
    CP_COMMIT();

    for (int kt = 0; kt < 32; kt++) {
        const int buf = kt & 1;
        CP_WAIT0();
        __syncthreads();
        if (kt + 1 < 32) { fill(kt + 1, buf ^ 1); }
        CP_COMMIT();

        const uint32_t* sK = asm_ + A_KV_OFF + buf * KVBUF_UINTS;
        const uint32_t* sV = sK + 32 * AQS_;

        // ---- S = Q K^T ----
        float S[2][4][4];
#pragma unroll
        for (int mt = 0; mt < 2; mt++)
#pragma unroll
            for (int nt = 0; nt < 4; nt++)
#pragma unroll
                for (int f = 0; f < 4; f++) S[mt][nt][f] = 0.0f;

#pragma unroll
        for (int h2 = 0; h2 < 4; h2++) {
            const int koff = 32 * (h2 >> 1) + 4 * (h2 & 1) + 8 * t;
            uint4 av[2][2];
#pragma unroll
            for (int mt = 0; mt < 2; mt++) {
                int r0 = wq0 + 16 * mt + g;
                av[mt][0] = *reinterpret_cast<const uint4*>(&sQ[r0 * AQS_ + koff]);
                av[mt][1] = *reinterpret_cast<const uint4*>(&sQ[(r0 + 8) * AQS_ + koff]);
            }
            uint4 bv[4];
#pragma unroll
            for (int nt = 0; nt < 4; nt++)
                bv[nt] = *reinterpret_cast<const uint4*>(&sK[(8 * nt + g) * AQS_ + koff]);
#pragma unroll
            for (int ss = 0; ss < 2; ss++) {
#pragma unroll
                for (int mt = 0; mt < 2; mt++) {
                    uint32_t a0 = (ss == 0) ? av[mt][0].x : av[mt][0].z;
                    uint32_t a2 = (ss == 0) ? av[mt][0].y : av[mt][0].w;
                    uint32_t a1 = (ss == 0) ? av[mt][1].x : av[mt][1].z;
                    uint32_t a3 = (ss == 0) ? av[mt][1].y : av[mt][1].w;
#pragma unroll
                    for (int nt = 0; nt < 4; nt++) {
                        uint32_t b0 = (ss == 0) ? bv[nt].x : bv[nt].z;
                        uint32_t b1 = (ss == 0) ? bv[nt].y : bv[nt].w;
                        MMA_TF32(S[mt][nt][0], S[mt][nt][1], S[mt][nt][2], S[mt][nt][3],
                                 a0, a1, a2, a3, b0, b1);
                    }
                }
            }
        }

        // ---- Online softmax (base-2, registers + quad shfl) ----
#pragma unroll
        for (int mt = 0; mt < 2; mt++) {
#pragma unroll
            for (int r = 0; r < 2; r++) {
                float mx = -1e30f;
#pragma unroll
                for (int nt = 0; nt < 4; nt++)
                    mx = fmaxf(mx, fmaxf(S[mt][nt][2 * r], S[mt][nt][2 * r + 1]));
                mx = fmaxf(mx, __shfl_xor_sync(0xffffffffu, mx, 1));
                mx = fmaxf(mx, __shfl_xor_sync(0xffffffffu, mx, 2));
                float mo = m_[mt][r];
                float mn = fmaxf(mo, mx);
                float alpha = exp2f(mo - mn);
                float sum = 0.0f;
#pragma unroll
                for (int nt = 0; nt < 4; nt++) {
                    float p0 = exp2f(S[mt][nt][2 * r] - mn);
                    float p1 = exp2f(S[mt][nt][2 * r + 1] - mn);
                    S[mt][nt][2 * r] = p0;
                    S[mt][nt][2 * r + 1] = p1;
                    sum += p0 + p1;
                }
                sum += __shfl_xor_sync(0xffffffffu, sum, 1);
                sum += __shfl_xor_sync(0xffffffffu, sum, 2);
                m_[mt][r] = mn;
                l_[mt][r] = l_[mt][r] * alpha + sum;
#pragma unroll
                for (int nd = 0; nd < 8; nd++) {
                    O[mt][nd][2 * r]     *= alpha;
                    O[mt][nd][2 * r + 1] *= alpha;
                }
            }
        }

        // ---- O += P V (register-P; B = scalar pairs from row-major sV) ----
#pragma unroll
        for (int kc = 0; kc < 4; kc++) {
            uint32_t a[2][4];
#pragma unroll
            for (int mt = 0; mt < 2; mt++) {
                a[mt][0] = f2tf32(S[mt][kc][0]);
                a[mt][1] = f2tf32(S[mt][kc][2]);
                a[mt][2] = f2tf32(S[mt][kc][1]);
                a[mt][3] = f2tf32(S[mt][kc][3]);
            }
            const uint32_t* vr0 = &sV[(8 * kc + 2 * t) * AQS_ + g];
            const uint32_t* vr1 = vr0 + AQS_;
#pragma unroll
            for (int nd = 0; nd < 8; nd++) {
                uint32_t b0 = vr0[8 * nd];
                uint32_t b1 = vr1[8 * nd];
#pragma unroll
                for (int mt = 0; mt < 2; mt++) {
                    MMA_TF32(O[mt][nd][0], O[mt][nd][1], O[mt][nd][2], O[mt][nd][3],
                             a[mt][0], a[mt][1], a[mt][2], a[mt][3], b0, b1);
                }
            }
        }
    }

    // ---- Normalize + write tf32-rounded ----
    const size_t outBase = ((size_t)bt * SEQ_ + q0) * INNER_ + (size_t)h * HD_;
#pragma unroll
    for (int mt = 0; mt < 2; mt++) {
#pragma unroll
        for (int r = 0; r < 2; r++) {
            float inv = 1.0f / l_[mt][r];
            int row = wq0 + 16 * mt + g + 8 * r;
#pragma unroll
            for (int nd = 0; nd < 8; nd++) {
                uint2 o = make_uint2(f2tf32(O[mt][nd][2 * r] * inv),
                                     f2tf32(O[mt][nd][2 * r + 1] * inv));
                *reinterpret_cast<uint2*>(&outb[outBase + (size_t)row * INNER_ + 8 * nd + 2 * t]) = o;
            }
        }
    }
}

// ---------------------------------------------------------------------------
extern "C" void kernel_launch(void* const* d_in, const int* in_sizes, int n_in,
                              void* d_out, int out_size)
{
    const float* x     = (const float*)d_in[0];
    const float* w_qkv = (const float*)d_in[1];
    const float* w_out = (const float*)d_in[2];
    const float* b_out = (const float*)d_in[3];
    float* out = (float*)d_out;

    float* qkv = nullptr; float* attn = nullptr;
    float* xr = nullptr;  float* wq = nullptr;  float* wo = nullptr;
    float2* rtab = nullptr;
    cudaGetSymbolAddress((void**)&qkv, g_qkv);
    cudaGetSymbolAddress((void**)&attn, g_attn);
    cudaGetSymbolAddress((void**)&xr, g_x);
    cudaGetSymbolAddress((void**)&wq, g_wq);
    cudaGetSymbolAddress((void**)&wo, g_wo);
    cudaGetSymbolAddress((void**)&rtab, g_rope);

    static bool attr_set = false;
    if (!attr_set) {
        cudaFuncSetAttribute(gemm_mma,
                             cudaFuncAttributeMaxDynamicSharedMemorySize, GEMM_SMEM_BYTES);
        cudaFuncSetAttribute(attn_mma,
                             cudaFuncAttributeMaxDynamicSharedMemorySize, ATTN_SMEM_BYTES);
        attr_set = true;
    }

    // 0) Fused prologue: rope table + tf32 rounding of x, w_qkv, w_out
    {
        int total = N4X + N4Q + N4O;
        prologue_kernel<<<(total + 255) / 256, 256>>>(x, xr, w_qkv, wq, w_out, wo, rtab);
    }

    // 1) QKV projection with fused RoPE + k,v tf32 rounding
    {
        dim3 grid(QKVN_ / 128, NTOK_ / 128);
        gemm_mma<<<grid, 256, GEMM_SMEM_BYTES>>>(xr, wq, nullptr, qkv, QKVN_, rtab, 1);
    }

    // 2) Attention (BQ=128, R12 config)
    {
        dim3 grid(SEQ_ / 128, BT_ * NH_);
        attn_mma<<<grid, 128, ATTN_SMEM_BYTES>>>(qkv, attn);
    }

    // 3) Output projection + bias
    {
        dim3 grid(INNER_ / 128, NTOK_ / 128);
        gemm_mma<<<grid, 256, GEMM_SMEM_BYTES>>>(attn, wo, b_out, out, INNER_, nullptr, 0);
    }
}

// round 16
// speedup vs baseline: 1.0010x; 1.0010x over previous
#include <cuda_runtime.h>
#include <math.h>
#include <stdint.h>

// Problem constants
#define BT_    16
#define NH_    8
#define HD_    64
#define SEQ_   1024
#define NTOK_  16384
#define DIM_   512
#define INNER_ 512
#define QKVN_  1536
#define GK_    512

#define PI_F 3.14159265358979323846f
#define LOG2E_F 1.4426950408889634f

// GEMM tiling: 128x128 tile, K-chunk 32, 3-stage cp.async pipeline, 2 CTA/SM
#define GSTRIDE 36
#define STAGE_FLOATS (2 * 128 * GSTRIDE)
#define STAGE_BYTES  (STAGE_FLOATS * 4)
#define GSTAGES 3
#define GEMM_SMEM_BYTES (GSTAGES * STAGE_BYTES)    // 110592

// Attention smem: BQ=128. sQ[128][68] + 2 x (sK[32][68] + sV[32][68]) -> 3 CTA/SM
#define AQS_ 68
#define A_SQ_OFF   0
#define A_KV_OFF   (128 * AQS_)
#define KVBUF_UINTS (2 * 32 * AQS_)
#define ATTN_SMEM_UINTS (A_KV_OFF + 2 * KVBUF_UINTS)
#define ATTN_SMEM_BYTES (ATTN_SMEM_UINTS * 4)      // 69632

// Scratch
__device__ float g_qkv[(size_t)NTOK_ * QKVN_];
__device__ float g_attn[(size_t)NTOK_ * INNER_];
__device__ float g_x[(size_t)NTOK_ * DIM_];
__device__ float g_wq[(size_t)QKVN_ * DIM_];
__device__ float g_wo[(size_t)INNER_ * DIM_];
__device__ float2 g_rope[32 * 32];                 // [pos][pair] -> (cos, sin)

// ---------------------------------------------------------------------------
__device__ __forceinline__ uint32_t f2tf32(float x) {
    uint32_t r;
    asm("cvt.rna.tf32.f32 %0, %1;" : "=r"(r) : "f"(x));
    return r;
}
__device__ __forceinline__ float tf32r(float x) { return __uint_as_float(f2tf32(x)); }
__device__ __forceinline__ uint32_t smem_u32(const void* p) {
    uint32_t a;
    asm("{ .reg .u64 t; cvta.to.shared.u64 t, %1; cvt.u32.u64 %0, t; }"
        : "=r"(a) : "l"(p));
    return a;
}
__device__ __forceinline__ void cp16(uint32_t saddr, const void* gaddr) {
    asm volatile("cp.async.cg.shared.global [%0], [%1], 16;"
                 :: "r"(saddr), "l"(gaddr) : "memory");
}
#define CP_COMMIT() asm volatile("cp.async.commit_group;" ::: "memory")
#define CP_WAIT1()  asm volatile("cp.async.wait_group 1;" ::: "memory")
#define CP_WAIT0()  asm volatile("cp.async.wait_group 0;" ::: "memory")

#define MMA_TF32(c0, c1, c2, c3, a0, a1, a2, a3, b0, b1) \
    asm volatile("mma.sync.aligned.m16n8k8.row.col.f32.tf32.tf32.f32 " \
        "{%0,%1,%2,%3}, {%4,%5,%6,%7}, {%8,%9}, {%0,%1,%2,%3};" \
        : "+f"(c0), "+f"(c1), "+f"(c2), "+f"(c3) \
        : "r"(a0), "r"(a1), "r"(a2), "r"(a3), "r"(b0), "r"(b1))

// ---------------------------------------------------------------------------
// Fused prologue: tf32-round x, w_qkv, w_out + build rope table, one launch.
// ---------------------------------------------------------------------------
#define N4X (NTOK_ * DIM_ / 4)
#define N4Q (QKVN_ * DIM_ / 4)
#define N4O (INNER_ * DIM_ / 4)

__global__ __launch_bounds__(256) void prologue_kernel(
    const float* __restrict__ x,  float* __restrict__ xr,
    const float* __restrict__ wq, float* __restrict__ wqr,
    const float* __restrict__ wo, float* __restrict__ wor,
    float2* __restrict__ tab)
{
    int i = blockIdx.x * blockDim.x + threadIdx.x;
    if (i < 1024) {
        int pidx = i >> 5;
        int p = i & 31;
        float base = (1.0f + (float)(p & 15) * (127.0f / 15.0f)) * PI_F;
        float pos = -1.0f + (float)pidx * (2.0f / 31.0f);
        float s, c;
        sincosf(pos * base, &s, &c);
        tab[i] = make_float2(c, s);
    }
    const float* src; float* dst; int idx;
    if (i < N4X)                 { src = x;  dst = xr;  idx = i; }
    else if (i < N4X + N4Q)      { src = wq; dst = wqr; idx = i - N4X; }
    else if (i < N4X + N4Q + N4O){ src = wo; dst = wor; idx = i - N4X - N4Q; }
    else return;
    float4 v = reinterpret_cast<const float4*>(src)[idx];
    uint4 u = make_uint4(f2tf32(v.x), f2tf32(v.y), f2tf32(v.z), f2tf32(v.w));
    reinterpret_cast<uint4*>(dst)[idx] = u;
}

// ---------------------------------------------------------------------------
// tf32 mma.sync GEMM, 3-stage cp.async pipeline, 2 CTAs/SM.
// Single barrier per K-iteration (top barrier orders prior compute vs refill).
// mode 0: C = A*B^T + bias. mode 1: fused RoPE on q,k cols + tf32 round k,v.
// ---------------------------------------------------------------------------
__global__ __launch_bounds__(256, 2) void gemm_mma(
    const float* __restrict__ A, const float* __restrict__ B,
    const float* __restrict__ bias, float* __restrict__ C, int N,
    const float2* __restrict__ rope_tab, int mode)
{
    extern __shared__ float smem[];
    const uint32_t sbase = smem_u32(smem);

    const int tid = threadIdx.x;
    const int wid = tid >> 5;
    const int lane = tid & 31;
    const int g = lane >> 2;
    const int t = lane & 3;
    const int bm = blockIdx.y * 128;
    const int bn = blockIdx.x * 128;
    const int mbase = (wid >> 2) * 64;
    const int nbase = (wid & 3) * 32;

    auto issue = [&](int stage, int k0) {
        uint32_t sA = sbase + (uint32_t)stage * STAGE_BYTES;
        uint32_t sB = sA + 128 * GSTRIDE * 4;
#pragma unroll
        for (int it = 0; it < 4; it++) {
            int idx = tid + it * 256;
            int row = idx >> 3;
            int seg = (idx & 7) << 2;
            uint32_t so = (uint32_t)(row * (GSTRIDE * 4) + seg * 4);
            cp16(sA + so, &A[(size_t)(bm + row) * GK_ + k0 + seg]);
            cp16(sB + so, &B[(size_t)(bn + row) * GK_ + k0 + seg]);
        }
    };

    float C0[4][4][4];
#pragma unroll
    for (int mt = 0; mt < 4; mt++)
#pragma unroll
        for (int nt = 0; nt < 4; nt++)
#pragma unroll
            for (int f = 0; f < 4; f++) C0[mt][nt][f] = 0.0f;

    issue(0, 0);  CP_COMMIT();
    issue(1, 32); CP_COMMIT();

    for (int kt = 0; kt < 16; kt++) {
        CP_WAIT1();
        __syncthreads();   // orders: (a) chunk kt data visible to all,
                           // (b) prior compute on stage (kt+2)%3 done before refill

        if (kt + 2 < 16) issue((kt + 2) % GSTAGES, (kt + 2) * 32);
        CP_COMMIT();

        const int buf = kt % GSTAGES;
        const uint32_t* As = reinterpret_cast<const uint32_t*>(smem) + buf * STAGE_FLOATS;
        const uint32_t* Bs = As + 128 * GSTRIDE;

#pragma unroll
        for (int half = 0; half < 2; half++) {
            uint4 av[4][2];
            uint4 bv[4];
#pragma unroll
            for (int mt = 0; mt < 4; mt++) {
                int r0 = mbase + mt * 16 + g;
                av[mt][0] = *reinterpret_cast<const uint4*>(&As[r0 * GSTRIDE + 8 * t + 4 * half]);
                av[mt][1] = *reinterpret_cast<const uint4*>(&As[(r0 + 8) * GSTRIDE + 8 * t + 4 * half]);
            }
#pragma unroll
            for (int nt = 0; nt < 4; nt++) {
                int rn = nbase + nt * 8 + g;
                bv[nt] = *reinterpret_cast<const uint4*>(&Bs[rn * GSTRIDE + 8 * t + 4 * half]);
            }
#pragma unroll
            for (int ss = 0; ss < 2; ss++) {
#pragma unroll
                for (int mt = 0; mt < 4; mt++) {
                    uint32_t a0 = (ss == 0) ? av[mt][0].x : av[mt][0].z;
                    uint32_t a2 = (ss == 0) ? av[mt][0].y : av[mt][0].w;
                    uint32_t a1 = (ss == 0) ? av[mt][1].x : av[mt][1].z;
                    uint32_t a3 = (ss == 0) ? av[mt][1].y : av[mt][1].w;
#pragma unroll
                    for (int nt = 0; nt < 4; nt++) {
                        uint32_t b0 = (ss == 0) ? bv[nt].x : bv[nt].z;
                        uint32_t b1 = (ss == 0) ? bv[nt].y : bv[nt].w;
                        MMA_TF32(C0[mt][nt][0], C0[mt][nt][1], C0[mt][nt][2], C0[mt][nt][3],
                                 a0, a1, a2, a3, b0, b1);
                    }
                }
            }
        }
        // no trailing barrier: next iteration's top barrier provides ordering
    }

    // ---- Epilogue ----
#pragma unroll
    for (int mt = 0; mt < 4; mt++) {
        int row0 = bm + mbase + mt * 16 + g;
#pragma unroll
        for (int nt = 0; nt < 4; nt++) {
            int col = bn + nbase + nt * 8 + 2 * t;
            float v00 = C0[mt][nt][0], v01 = C0[mt][nt][1];
            float v10 = C0[mt][nt][2], v11 = C0[mt][nt][3];
            if (mode == 0) {
                float bx = 0.f, by = 0.f;
                if (bias) { bx = bias[col]; by = bias[col + 1]; }
                v00 += bx; v01 += by; v10 += bx; v11 += by;
            } else {
                if (col < 1024) {
                    int p = (col >> 1) & 31;
                    int pidx0 = (p < 16) ? ((row0 >> 5) & 31) : (row0 & 31);
                    int pidx1 = (p < 16) ? (((row0 + 8) >> 5) & 31) : ((row0 + 8) & 31);
                    float2 cs0 = rope_tab[(pidx0 << 5) | p];
                    float2 cs1 = rope_tab[(pidx1 << 5) | p];
                    float r00 = v00 * cs0.x - v01 * cs0.y;
                    float r01 = v01 * cs0.x + v00 * cs0.y;
                    float r10 = v10 * cs1.x - v11 * cs1.y;
                    float r11 = v11 * cs1.x + v10 * cs1.y;
                    if (col >= 512) {
                        r00 = tf32r(r00); r01 = tf32r(r01);
                        r10 = tf32r(r10); r11 = tf32r(r11);
                    }
                    v00 = r00; v01 = r01; v10 = r10; v11 = r11;
                } else {
                    v00 = tf32r(v00); v01 = tf32r(v01);
                    v10 = tf32r(v10); v11 = tf32r(v11);
                }
            }
            *reinterpret_cast<float2*>(&C[(size_t)row0 * N + col]) = make_float2(v00, v01);
            *reinterpret_cast<float2*>(&C[(size_t)(row0 + 8) * N + col]) = make_float2(v10, v11);
        }
    }
}

// ---------------------------------------------------------------------------
// Flash attention, tf32 mma.sync. 128 threads (4 warps x 32 q-rows),
// BK=32 KV tiles, cp.async double-buffered, row-major sV, register-P trick,
// 3 CTAs/SM. (Exact R12 configuration — best measured.)
// ---------------------------------------------------------------------------
__global__ __launch_bounds__(128, 3) void attn_mma(
    const float* __restrict__ qkv, float* __restrict__ outb)
{
    extern __shared__ uint32_t asm_[];
    uint32_t* sQ = asm_ + A_SQ_OFF;     // [128][68] tf32 (scaled)
    const uint32_t sbase = smem_u32(asm_);

    const int bh = blockIdx.y;
    const int bt = bh >> 3;
    const int h  = bh & 7;
    const int q0 = blockIdx.x * 128;
    const int tid = threadIdx.x;
    const int wid = tid >> 5;           // 0..3
    const int lane = tid & 31;
    const int g = lane >> 2;
    const int t = lane & 3;
    const int wq0 = wid * 32;

    const float qscale = 0.125f * LOG2E_F;

    // ---- Q -> sQ (scaled tf32) ----
    const size_t baseQ = ((size_t)bt * SEQ_ + q0) * QKVN_ + (size_t)h * HD_;
#pragma unroll
    for (int it = 0; it < 16; it++) {
        int idx = tid + it * 128;
        int r  = idx >> 4;
        int c4 = (idx & 15) << 2;
        float4 v = *reinterpret_cast<const float4*>(&qkv[baseQ + (size_t)r * QKVN_ + c4]);
        uint4 u = make_uint4(f2tf32(v.x * qscale), f2tf32(v.y * qscale),
                             f2tf32(v.z * qscale), f2tf32(v.w * qscale));
        *reinterpret_cast<uint4*>(&sQ[r * AQS_ + c4]) = u;
    }

    const size_t baseKV0 = (size_t)bt * SEQ_ * QKVN_ + 512 + (size_t)h * HD_;
    const int ldr = tid >> 4;               // 0..7
    const int ldc4 = (tid & 15) << 2;

    auto fill = [&](int kt, int buf) {
        const float* pK = &qkv[baseKV0 + (size_t)(kt * 32) * QKVN_];
        const float* pV = pK + 512;
        uint32_t ko = (uint32_t)(A_KV_OFF + buf * KVBUF_UINTS);
        uint32_t vo = ko + 32 * AQS_;
#pragma unroll
        for (int it = 0; it < 4; it++) {
            int r = ldr + it * 8;           // 0..31
            cp16(sbase + (ko + r * AQS_ + ldc4) * 4, &pK[(size_t)r * QKVN_ + ldc4]);
            cp16(sbase + (vo + r * AQS_ + ldc4) * 4, &pV[(size_t)r * QKVN_ + ldc4]);
        }
    };

    float O[2][8][4];
    float m_[2][2], l_[2][2];
#pragma unroll
    for (int mt = 0; mt < 2; mt++) {
#pragma unroll
        for (int r = 0; r < 2; r++) { m_[mt][r] = -1e30f; l_[mt][r] = 0.0f; }
#pragma unroll
        for (int nd = 0; nd < 8; nd++)
#pragma unroll
            for (int f = 0; f < 4; f++) O[mt][nd][f] = 0.0f;
    }

    fill(0, 0);
    CP_COMMIT();

    for (int kt = 0; kt < 32; kt++) {
        const int buf = kt & 1;
        CP_WAIT0();
        __syncthreads();
        if (kt + 1 < 32) { fill(kt + 1, buf ^ 1); }
        CP_COMMIT();

        const uint32_t* sK = asm_ + A_KV_OFF + buf * KVBUF_UINTS;
        const uint32_t* sV = sK + 32 * AQS_;

        // ---- S = Q K^T ----
        float S[2][4][4];
#pragma unroll
        for (int mt = 0; mt < 2; mt++)
#pragma unroll
            for (int nt = 0; nt < 4; nt++)
#pragma unroll
                for (int f = 0; f < 4; f++) S[mt][nt][f] = 0.0f;

#pragma unroll
        for (int h2 = 0; h2 < 4; h2++) {
            const int koff = 32 * (h2 >> 1) + 4 * (h2 & 1) + 8 * t;
            uint4 av[2][2];
#pragma unroll
            for (int mt = 0; mt < 2; mt++) {
                int r0 = wq0 + 16 * mt + g;
                av[mt][0] = *reinterpret_cast<const uint4*>(&sQ[r0 * AQS_ + koff]);
                av[mt][1] = *reinterpret_cast<const uint4*>(&sQ[(r0 + 8) * AQS_ + koff]);
            }
            uint4 bv[4];
#pragma unroll
            for (int nt = 0; nt < 4; nt++)
                bv[nt] = *reinterpret_cast<const uint4*>(&sK[(8 * nt + g) * AQS_ + koff]);
#pragma unroll
            for (int ss = 0; ss < 2; ss++) {
#pragma unroll
                for (int mt = 0; mt < 2; mt++) {
                    uint32_t a0 = (ss == 0) ? av[mt][0].x : av[mt][0].z;
                    uint32_t a2 = (ss == 0) ? av[mt][0].y : av[mt][0].w;
                    uint32_t a1 = (ss == 0) ? av[mt][1].x : av[mt][1].z;
                    uint32_t a3 = (ss == 0) ? av[mt][1].y : av[mt][1].w;
#pragma unroll
                    for (int nt = 0; nt < 4; nt++) {
                        uint32_t b0 = (ss == 0) ? bv[nt].x : bv[nt].z;
                        uint32_t b1 = (ss == 0) ? bv[nt].y : bv[nt].w;
                        MMA_TF32(S[mt][nt][0], S[mt][nt][1], S[mt][nt][2], S[mt][nt][3],
                                 a0, a1, a2, a3, b0, b1);
                    }
                }
            }
        }

        // ---- Online softmax (base-2, registers + quad shfl) ----
#pragma unroll
        for (int mt = 0; mt < 2; mt++) {
#pragma unroll
            for (int r = 0; r < 2; r++) {
                float mx = -1e30f;
#pragma unroll
                for (int nt = 0; nt < 4; nt++)
                    mx = fmaxf(mx, fmaxf(S[mt][nt][2 * r], S[mt][nt][2 * r + 1]));
                mx = fmaxf(mx, __shfl_xor_sync(0xffffffffu, mx, 1));
                mx = fmaxf(mx, __shfl_xor_sync(0xffffffffu, mx, 2));
                float mo = m_[mt][r];
                float mn = fmaxf(mo, mx);
                float alpha = exp2f(mo - mn);
                float sum = 0.0f;
#pragma unroll
                for (int nt = 0; nt < 4; nt++) {
                    float p0 = exp2f(S[mt][nt][2 * r] - mn);
                    float p1 = exp2f(S[mt][nt][2 * r + 1] - mn);
                    S[mt][nt][2 * r] = p0;
                    S[mt][nt][2 * r + 1] = p1;
                    sum += p0 + p1;
                }
                sum += __shfl_xor_sync(0xffffffffu, sum, 1);
                sum += __shfl_xor_sync(0xffffffffu, sum, 2);
                m_[mt][r] = mn;
                l_[mt][r] = l_[mt][r] * alpha + sum;
#pragma unroll
                for (int nd = 0; nd < 8; nd++) {
                    O[mt][nd][2 * r]     *= alpha;
                    O[mt][nd][2 * r + 1] *= alpha;
                }
            }
        }

        // ---- O += P V (register-P; B = scalar pairs from row-major sV) ----
#pragma unroll
        for (int kc = 0; kc < 4; kc++) {
            uint32_t a[2][4];
#pragma unroll
            for (int mt = 0; mt < 2; mt++) {
                a[mt][0] = f2tf32(S[mt][kc][0]);
                a[mt][1] = f2tf32(S[mt][kc][2]);
                a[mt][2] = f2tf32(S[mt][kc][1]);
                a[mt][3] = f2tf32(S[mt][kc][3]);
            }
            const uint32_t* vr0 = &sV[(8 * kc + 2 * t) * AQS_ + g];
            const uint32_t* vr1 = vr0 + AQS_;
#pragma unroll
            for (int nd = 0; nd < 8; nd++) {
                uint32_t b0 = vr0[8 * nd];
                uint32_t b1 = vr1[8 * nd];
#pragma unroll
                for (int mt = 0; mt < 2; mt++) {
                    MMA_TF32(O[mt][nd][0], O[mt][nd][1], O[mt][nd][2], O[mt][nd][3],
                             a[mt][0], a[mt][1], a[mt][2], a[mt][3], b0, b1);
                }
            }
        }
    }

    // ---- Normalize + write tf32-rounded ----
    const size_t outBase = ((size_t)bt * SEQ_ + q0) * INNER_ + (size_t)h * HD_;
#pragma unroll
    for (int mt = 0; mt < 2; mt++) {
#pragma unroll
        for (int r = 0; r < 2; r++) {
            float inv = 1.0f / l_[mt][r];
            int row = wq0 + 16 * mt + g + 8 * r;
#pragma unroll
            for (int nd = 0; nd < 8; nd++) {
                uint2 o = make_uint2(f2tf32(O[mt][nd][2 * r] * inv),
                                     f2tf32(O[mt][nd][2 * r + 1] * inv));
                *reinterpret_cast<uint2*>(&outb[outBase + (size_t)row * INNER_ + 8 * nd + 2 * t]) = o;
            }
        }
    }
}

// ---------------------------------------------------------------------------
extern "C" void kernel_launch(void* const* d_in, const int* in_sizes, int n_in,
                              void* d_out, int out_size)
{
    const float* x     = (const float*)d_in[0];
    const float* w_qkv = (const float*)d_in[1];
    const float* w_out = (const float*)d_in[2];
    const float* b_out = (const float*)d_in[3];
    float* out = (float*)d_out;

    float* qkv = nullptr; float* attn = nullptr;
    float* xr = nullptr;  float* wq = nullptr;  float* wo = nullptr;
    float2* rtab = nullptr;
    cudaGetSymbolAddress((void**)&qkv, g_qkv);
    cudaGetSymbolAddress((void**)&attn, g_attn);
    cudaGetSymbolAddress((void**)&xr, g_x);
    cudaGetSymbolAddress((void**)&wq, g_wq);
    cudaGetSymbolAddress((void**)&wo, g_wo);
    cudaGetSymbolAddress((void**)&rtab, g_rope);

    static bool attr_set = false;
    if (!attr_set) {
        cudaFuncSetAttribute(gemm_mma,
                             cudaFuncAttributeMaxDynamicSharedMemorySize, GEMM_SMEM_BYTES);
        cudaFuncSetAttribute(attn_mma,
                             cudaFuncAttributeMaxDynamicSharedMemorySize, ATTN_SMEM_BYTES);
        attr_set = true;
    }

    // 0) Fused prologue: rope table + tf32 rounding of x, w_qkv, w_out
    {
        int total = N4X + N4Q + N4O;
        prologue_kernel<<<(total + 255) / 256, 256>>>(x, xr, w_qkv, wq, w_out, wo, rtab);
    }

    // 1) QKV projection with fused RoPE + k,v tf32 rounding
    {
        dim3 grid(QKVN_ / 128, NTOK_ / 128);
        gemm_mma<<<grid, 256, GEMM_SMEM_BYTES>>>(xr, wq, nullptr, qkv, QKVN_, rtab, 1);
    }

    // 2) Attention (BQ=128, R12 config)
    {
        dim3 grid(SEQ_ / 128, BT_ * NH_);
        attn_mma<<<grid, 128, ATTN_SMEM_BYTES>>>(qkv, attn);
    }

    // 3) Output projection + bias
    {
        dim3 grid(INNER_ / 128, NTOK_ / 128);
        gemm_mma<<<grid, 256, GEMM_SMEM_BYTES>>>(attn, wo, b_out, out, INNER_, nullptr, 0);
    }
}

// round 17
// speedup vs baseline: 1.0027x; 1.0018x over previous
#include <cuda_runtime.h>
#include <math.h>
#include <stdint.h>

// Problem constants
#define BT_    16
#define NH_    8
#define HD_    64
#define SEQ_   1024
#define NTOK_  16384
#define DIM_   512
#define INNER_ 512
#define QKVN_  1536
#define GK_    512

#define PI_F 3.14159265358979323846f
#define LOG2E_F 1.4426950408889634f

// GEMM tiling: 128x128 tile, K-chunk 32, 3-stage cp.async pipeline, 2 CTA/SM
#define GSTRIDE 36
#define STAGE_FLOATS (2 * 128 * GSTRIDE)
#define STAGE_BYTES  (STAGE_FLOATS * 4)
#define GSTAGES 3
#define GEMM_SMEM_BYTES (GSTAGES * STAGE_BYTES)    // 110592

// Attention smem: BQ=128. sQ[128][68] + 2 x (sK[32][68] + sV[32][68]) -> 3 CTA/SM
#define AQS_ 68
#define A_SQ_OFF   0
#define A_KV_OFF   (128 * AQS_)
#define KVBUF_UINTS (2 * 32 * AQS_)
#define ATTN_SMEM_UINTS (A_KV_OFF + 2 * KVBUF_UINTS)
#define ATTN_SMEM_BYTES (ATTN_SMEM_UINTS * 4)      // 69632

// Scratch
__device__ float g_qkv[(size_t)NTOK_ * QKVN_];
__device__ float g_attn[(size_t)NTOK_ * INNER_];
__device__ float g_x[(size_t)NTOK_ * DIM_];
__device__ float g_wq[(size_t)QKVN_ * DIM_];
__device__ float g_wo[(size_t)INNER_ * DIM_];
__device__ float2 g_rope[32 * 32];                 // [pos][pair] -> (cos, sin)

// ---------------------------------------------------------------------------
__device__ __forceinline__ uint32_t f2tf32(float x) {
    uint32_t r;
    asm("cvt.rna.tf32.f32 %0, %1;" : "=r"(r) : "f"(x));
    return r;
}
__device__ __forceinline__ float tf32r(float x) { return __uint_as_float(f2tf32(x)); }
__device__ __forceinline__ uint32_t smem_u32(const void* p) {
    uint32_t a;
    asm("{ .reg .u64 t; cvta.to.shared.u64 t, %1; cvt.u32.u64 %0, t; }"
        : "=r"(a) : "l"(p));
    return a;
}
__device__ __forceinline__ void cp16(uint32_t saddr, const void* gaddr) {
    asm volatile("cp.async.cg.shared.global [%0], [%1], 16;"
                 :: "r"(saddr), "l"(gaddr) : "memory");
}
#define CP_COMMIT() asm volatile("cp.async.commit_group;" ::: "memory")
#define CP_WAIT1()  asm volatile("cp.async.wait_group 1;" ::: "memory")
#define CP_WAIT0()  asm volatile("cp.async.wait_group 0;" ::: "memory")

#define MMA_TF32(c0, c1, c2, c3, a0, a1, a2, a3, b0, b1) \
    asm volatile("mma.sync.aligned.m16n8k8.row.col.f32.tf32.tf32.f32 " \
        "{%0,%1,%2,%3}, {%4,%5,%6,%7}, {%8,%9}, {%0,%1,%2,%3};" \
        : "+f"(c0), "+f"(c1), "+f"(c2), "+f"(c3) \
        : "r"(a0), "r"(a1), "r"(a2), "r"(a3), "r"(b0), "r"(b1))

// ---------------------------------------------------------------------------
// Fused prologue: tf32-round x, w_qkv, w_out + build rope table, one launch.
// ---------------------------------------------------------------------------
#define N4X (NTOK_ * DIM_ / 4)
#define N4Q (QKVN_ * DIM_ / 4)
#define N4O (INNER_ * DIM_ / 4)

__global__ __launch_bounds__(256) void prologue_kernel(
    const float* __restrict__ x,  float* __restrict__ xr,
    const float* __restrict__ wq, float* __restrict__ wqr,
    const float* __restrict__ wo, float* __restrict__ wor,
    float2* __restrict__ tab)
{
    int i = blockIdx.x * blockDim.x + threadIdx.x;
    if (i < 1024) {
        int pidx = i >> 5;
        int p = i & 31;
        float base = (1.0f + (float)(p & 15) * (127.0f / 15.0f)) * PI_F;
        float pos = -1.0f + (float)pidx * (2.0f / 31.0f);
        float s, c;
        sincosf(pos * base, &s, &c);
        tab[i] = make_float2(c, s);
    }
    const float* src; float* dst; int idx;
    if (i < N4X)                 { src = x;  dst = xr;  idx = i; }
    else if (i < N4X + N4Q)      { src = wq; dst = wqr; idx = i - N4X; }
    else if (i < N4X + N4Q + N4O){ src = wo; dst = wor; idx = i - N4X - N4Q; }
    else return;
    float4 v = reinterpret_cast<const float4*>(src)[idx];
    uint4 u = make_uint4(f2tf32(v.x), f2tf32(v.y), f2tf32(v.z), f2tf32(v.w));
    reinterpret_cast<uint4*>(dst)[idx] = u;
}

// ---------------------------------------------------------------------------
// tf32 mma.sync GEMM, 3-stage cp.async pipeline, 2 CTAs/SM.
// Single barrier per K-iteration (top barrier orders prior compute vs refill).
// mode 0: C = A*B^T + bias. mode 1: fused RoPE on q,k cols + tf32 round k,v.
// ---------------------------------------------------------------------------
__global__ __launch_bounds__(256, 2) void gemm_mma(
    const float* __restrict__ A, const float* __restrict__ B,
    const float* __restrict__ bias, float* __restrict__ C, int N,
    const float2* __restrict__ rope_tab, int mode)
{
    extern __shared__ float smem[];
    const uint32_t sbase = smem_u32(smem);

    const int tid = threadIdx.x;
    const int wid = tid >> 5;
    const int lane = tid & 31;
    const int g = lane >> 2;
    const int t = lane & 3;
    const int bm = blockIdx.y * 128;
    const int bn = blockIdx.x * 128;
    const int mbase = (wid >> 2) * 64;
    const int nbase = (wid & 3) * 32;

    auto issue = [&](int stage, int k0) {
        uint32_t sA = sbase + (uint32_t)stage * STAGE_BYTES;
        uint32_t sB = sA + 128 * GSTRIDE * 4;
#pragma unroll
        for (int it = 0; it < 4; it++) {
            int idx = tid + it * 256;
            int row = idx >> 3;
            int seg = (idx & 7) << 2;
            uint32_t so = (uint32_t)(row * (GSTRIDE * 4) + seg * 4);
            cp16(sA + so, &A[(size_t)(bm + row) * GK_ + k0 + seg]);
            cp16(sB + so, &B[(size_t)(bn + row) * GK_ + k0 + seg]);
        }
    };

    float C0[4][4][4];
#pragma unroll
    for (int mt = 0; mt < 4; mt++)
#pragma unroll
        for (int nt = 0; nt < 4; nt++)
#pragma unroll
            for (int f = 0; f < 4; f++) C0[mt][nt][f] = 0.0f;

    issue(0, 0);  CP_COMMIT();
    issue(1, 32); CP_COMMIT();

    for (int kt = 0; kt < 16; kt++) {
        CP_WAIT1();
        __syncthreads();   // orders: (a) chunk kt data visible to all,
                           // (b) prior compute on stage (kt+2)%3 done before refill

        if (kt + 2 < 16) issue((kt + 2) % GSTAGES, (kt + 2) * 32);
        CP_COMMIT();

        const int buf = kt % GSTAGES;
        const uint32_t* As = reinterpret_cast<const uint32_t*>(smem) + buf * STAGE_FLOATS;
        const uint32_t* Bs = As + 128 * GSTRIDE;

#pragma unroll
        for (int half = 0; half < 2; half++) {
            uint4 av[4][2];
            uint4 bv[4];
#pragma unroll
            for (int mt = 0; mt < 4; mt++) {
                int r0 = mbase + mt * 16 + g;
                av[mt][0] = *reinterpret_cast<const uint4*>(&As[r0 * GSTRIDE + 8 * t + 4 * half]);
                av[mt][1] = *reinterpret_cast<const uint4*>(&As[(r0 + 8) * GSTRIDE + 8 * t + 4 * half]);
            }
#pragma unroll
            for (int nt = 0; nt < 4; nt++) {
                int rn = nbase + nt * 8 + g;
                bv[nt] = *reinterpret_cast<const uint4*>(&Bs[rn * GSTRIDE + 8 * t + 4 * half]);
            }
#pragma unroll
            for (int ss = 0; ss < 2; ss++) {
#pragma unroll
                for (int mt = 0; mt < 4; mt++) {
                    uint32_t a0 = (ss == 0) ? av[mt][0].x : av[mt][0].z;
                    uint32_t a2 = (ss == 0) ? av[mt][0].y : av[mt][0].w;
                    uint32_t a1 = (ss == 0) ? av[mt][1].x : av[mt][1].z;
                    uint32_t a3 = (ss == 0) ? av[mt][1].y : av[mt][1].w;
#pragma unroll
                    for (int nt = 0; nt < 4; nt++) {
                        uint32_t b0 = (ss == 0) ? bv[nt].x : bv[nt].z;
                        uint32_t b1 = (ss == 0) ? bv[nt].y : bv[nt].w;
                        MMA_TF32(C0[mt][nt][0], C0[mt][nt][1], C0[mt][nt][2], C0[mt][nt][3],
                                 a0, a1, a2, a3, b0, b1);
                    }
                }
            }
        }
        // no trailing barrier: next iteration's top barrier provides ordering
    }

    // ---- Epilogue ----
#pragma unroll
    for (int mt = 0; mt < 4; mt++) {
        int row0 = bm + mbase + mt * 16 + g;
#pragma unroll
        for (int nt = 0; nt < 4; nt++) {
            int col = bn + nbase + nt * 8 + 2 * t;
            float v00 = C0[mt][nt][0], v01 = C0[mt][nt][1];
            float v10 = C0[mt][nt][2], v11 = C0[mt][nt][3];
            if (mode == 0) {
                float bx = 0.f, by = 0.f;
                if (bias) { bx = bias[col]; by = bias[col + 1]; }
                v00 += bx; v01 += by; v10 += bx; v11 += by;
            } else {
                if (col < 1024) {
                    int p = (col >> 1) & 31;
                    int pidx0 = (p < 16) ? ((row0 >> 5) & 31) : (row0 & 31);
                    int pidx1 = (p < 16) ? (((row0 + 8) >> 5) & 31) : ((row0 + 8) & 31);
                    float2 cs0 = rope_tab[(pidx0 << 5) | p];
                    float2 cs1 = rope_tab[(pidx1 << 5) | p];
                    float r00 = v00 * cs0.x - v01 * cs0.y;
                    float r01 = v01 * cs0.x + v00 * cs0.y;
                    float r10 = v10 * cs1.x - v11 * cs1.y;
                    float r11 = v11 * cs1.x + v10 * cs1.y;
                    if (col >= 512) {
                        r00 = tf32r(r00); r01 = tf32r(r01);
                        r10 = tf32r(r10); r11 = tf32r(r11);
                    }
                    v00 = r00; v01 = r01; v10 = r10; v11 = r11;
                } else {
                    v00 = tf32r(v00); v01 = tf32r(v01);
                    v10 = tf32r(v10); v11 = tf32r(v11);
                }
            }
            *reinterpret_cast<float2*>(&C[(size_t)row0 * N + col]) = make_float2(v00, v01);
            *reinterpret_cast<float2*>(&C[(size_t)(row0 + 8) * N + col]) = make_float2(v10, v11);
        }
    }
}

// ---------------------------------------------------------------------------
// Flash attention, tf32 mma.sync. 128 threads (4 warps x 32 q-rows),
// BK=32 KV tiles, cp.async double-buffered, row-major sV, register-P trick,
// 3 CTAs/SM. (Exact R12 configuration — best measured.)
// ---------------------------------------------------------------------------
__global__ __launch_bounds__(128, 3) void attn_mma(
    const float* __restrict__ qkv, float* __restrict__ outb)
{
    extern __shared__ uint32_t asm_[];
    uint32_t* sQ = asm_ + A_SQ_OFF;     // [128][68] tf32 (scaled)
    const uint32_t sbase = smem_u32(asm_);

    const int bh = blockIdx.y;
    const int bt = bh >> 3;
    const int h  = bh & 7;
    const int q0 = blockIdx.x * 128;
    const int tid = threadIdx.x;
    const int wid = tid >> 5;           // 0..3
    const int lane = tid & 31;
    const int g = lane >> 2;
    const int t = lane & 3;
    const int wq0 = wid * 32;

    const float qscale = 0.125f * LOG2E_F;

    // ---- Q -> sQ (scaled tf32) ----
    const size_t baseQ = ((size_t)bt * SEQ_ + q0) * QKVN_ + (size_t)h * HD_;
#pragma unroll
    for (int it = 0; it < 16; it++) {
        int idx = tid + it * 128;
        int r  = idx >> 4;
        int c4 = (idx & 15) << 2;
        float4 v = *reinterpret_cast<const float4*>(&qkv[baseQ + (size_t)r * QKVN_ + c4]);
        uint4 u = make_uint4(f2tf32(v.x * qscale), f2tf32(v.y * qscale),
                             f2tf32(v.z * qscale), f2tf32(v.w * qscale));
        *reinterpret_cast<uint4*>(&sQ[r * AQS_ + c4]) = u;
    }

    const size_t baseKV0 = (size_t)bt * SEQ_ * QKVN_ + 512 + (size_t)h * HD_;
    const int ldr = tid >> 4;               // 0..7
    const int ldc4 = (tid & 15) << 2;

    auto fill = [&](int kt, int buf) {
        const float* pK = &qkv[baseKV0 + (size_t)(kt * 32) * QKVN_];
        const float* pV = pK + 512;
        uint32_t ko = (uint32_t)(A_KV_OFF + buf * KVBUF_UINTS);
        uint32_t vo = ko + 32 * AQS_;
#pragma unroll
        for (int it = 0; it < 4; it++) {
            int r = ldr + it * 8;           // 0..31
            cp16(sbase + (ko + r * AQS_ + ldc4) * 4, &pK[(size_t)r * QKVN_ + ldc4]);
            cp16(sbase + (vo + r * AQS_ + ldc4) * 4, &pV[(size_t)r * QKVN_ + ldc4]);
        }
    };

    float O[2][8][4];
    float m_[2][2], l_[2][2];
#pragma unroll
    for (int mt = 0; mt < 2; mt++) {
#pragma unroll
        for (int r = 0; r < 2; r++) { m_[mt][r] = -1e30f; l_[mt][r] = 0.0f; }
#pragma unroll
        for (int nd = 0; nd < 8; nd++)
#pragma unroll
            for (int f = 0; f < 4; f++) O[mt][nd][f] = 0.0f;
    }

    fill(0, 0);
    CP_COMMIT();

    for (int kt = 0; kt < 32; kt++) {
        const int buf = kt & 1;
        CP_WAIT0();
        __syncthreads();
        if (kt + 1 < 32) { fill(kt + 1, buf ^ 1); }
        CP_COMMIT();

        const uint32_t* sK = asm_ + A_KV_OFF + buf * KVBUF_UINTS;
        const uint32_t* sV = sK + 32 * AQS_;

        // ---- S = Q K^T ----
        float S[2][4][4];
#pragma unroll
        for (int mt = 0; mt < 2; mt++)
#pragma unroll
            for (int nt = 0; nt < 4; nt++)
#pragma unroll
                for (int f = 0; f < 4; f++) S[mt][nt][f] = 0.0f;

#pragma unroll
        for (int h2 = 0; h2 < 4; h2++) {
            const int koff = 32 * (h2 >> 1) + 4 * (h2 & 1) + 8 * t;
            uint4 av[2][2];
#pragma unroll
            for (int mt = 0; mt < 2; mt++) {
                int r0 = wq0 + 16 * mt + g;
                av[mt][0] = *reinterpret_cast<const uint4*>(&sQ[r0 * AQS_ + koff]);
                av[mt][1] = *reinterpret_cast<const uint4*>(&sQ[(r0 + 8) * AQS_ + koff]);
            }
            uint4 bv[4];
#pragma unroll
            for (int nt = 0; nt < 4; nt++)
                bv[nt] = *reinterpret_cast<const uint4*>(&sK[(8 * nt + g) * AQS_ + koff]);
#pragma unroll
            for (int ss = 0; ss < 2; ss++) {
#pragma unroll
                for (int mt = 0; mt < 2; mt++) {
                    uint32_t a0 = (ss == 0) ? av[mt][0].x : av[mt][0].z;
                    uint32_t a2 = (ss == 0) ? av[mt][0].y : av[mt][0].w;
                    uint32_t a1 = (ss == 0) ? av[mt][1].x : av[mt][1].z;
                    uint32_t a3 = (ss == 0) ? av[mt][1].y : av[mt][1].w;
#pragma unroll
                    for (int nt = 0; nt < 4; nt++) {
                        uint32_t b0 = (ss == 0) ? bv[nt].x : bv[nt].z;
                        uint32_t b1 = (ss == 0) ? bv[nt].y : bv[nt].w;
                        MMA_TF32(S[mt][nt][0], S[mt][nt][1], S[mt][nt][2], S[mt][nt][3],
                                 a0, a1, a2, a3, b0, b1);
                    }
                }
            }
        }

        // ---- Online softmax (base-2, registers + quad shfl) ----
#pragma unroll
        for (int mt = 0; mt < 2; mt++) {
#pragma unroll
            for (int r = 0; r < 2; r++) {
                float mx = -1e30f;
#pragma unroll
                for (int nt = 0; nt < 4; nt++)
                    mx = fmaxf(mx, fmaxf(S[mt][nt][2 * r], S[mt][nt][2 * r + 1]));
                mx = fmaxf(mx, __shfl_xor_sync(0xffffffffu, mx, 1));
                mx = fmaxf(mx, __shfl_xor_sync(0xffffffffu, mx, 2));
                float mo = m_[mt][r];
                float mn = fmaxf(mo, mx);
                float alpha = exp2f(mo - mn);
                float sum = 0.0f;
#pragma unroll
                for (int nt = 0; nt < 4; nt++) {
                    float p0 = exp2f(S[mt][nt][2 * r] - mn);
                    float p1 = exp2f(S[mt][nt][2 * r + 1] - mn);
                    S[mt][nt][2 * r] = p0;
                    S[mt][nt][2 * r + 1] = p1;
                    sum += p0 + p1;
                }
                sum += __shfl_xor_sync(0xffffffffu, sum, 1);
                sum += __shfl_xor_sync(0xffffffffu, sum, 2);
                m_[mt][r] = mn;
                l_[mt][r] = l_[mt][r] * alpha + sum;
#pragma unroll
                for (int nd = 0; nd < 8; nd++) {
                    O[mt][nd][2 * r]     *= alpha;
                    O[mt][nd][2 * r + 1] *= alpha;
                }
            }
        }

        // ---- O += P V (register-P; B = scalar pairs from row-major sV) ----
#pragma unroll
        for (int kc = 0; kc < 4; kc++) {
            uint32_t a[2][4];
#pragma unroll
            for (int mt = 0; mt < 2; mt++) {
                a[mt][0] = f2tf32(S[mt][kc][0]);
                a[mt][1] = f2tf32(S[mt][kc][2]);
                a[mt][2] = f2tf32(S[mt][kc][1]);
                a[mt][3] = f2tf32(S[mt][kc][3]);
            }
            const uint32_t* vr0 = &sV[(8 * kc + 2 * t) * AQS_ + g];
            const uint32_t* vr1 = vr0 + AQS_;
#pragma unroll
            for (int nd = 0; nd < 8; nd++) {
                uint32_t b0 = vr0[8 * nd];
                uint32_t b1 = vr1[8 * nd];
#pragma unroll
                for (int mt = 0; mt < 2; mt++) {
                    MMA_TF32(O[mt][nd][0], O[mt][nd][1], O[mt][nd][2], O[mt][nd][3],
                             a[mt][0], a[mt][1], a[mt][2], a[mt][3], b0, b1);
                }
            }
        }
    }

    // ---- Normalize + write tf32-rounded ----
    const size_t outBase = ((size_t)bt * SEQ_ + q0) * INNER_ + (size_t)h * HD_;
#pragma unroll
    for (int mt = 0; mt < 2; mt++) {
#pragma unroll
        for (int r = 0; r < 2; r++) {
            float inv = 1.0f / l_[mt][r];
            int row = wq0 + 16 * mt + g + 8 * r;
#pragma unroll
            for (int nd = 0; nd < 8; nd++) {
                uint2 o = make_uint2(f2tf32(O[mt][nd][2 * r] * inv),
                                     f2tf32(O[mt][nd][2 * r + 1] * inv));
                *reinterpret_cast<uint2*>(&outb[outBase + (size_t)row * INNER_ + 8 * nd + 2 * t]) = o;
            }
        }
    }
}

// ---------------------------------------------------------------------------
extern "C" void kernel_launch(void* const* d_in, const int* in_sizes, int n_in,
                              void* d_out, int out_size)
{
    const float* x     = (const float*)d_in[0];
    const float* w_qkv = (const float*)d_in[1];
    const float* w_out = (const float*)d_in[2];
    const float* b_out = (const float*)d_in[3];
    float* out = (float*)d_out;

    float* qkv = nullptr; float* attn = nullptr;
    float* xr = nullptr;  float* wq = nullptr;  float* wo = nullptr;
    float2* rtab = nullptr;
    cudaGetSymbolAddress((void**)&qkv, g_qkv);
    cudaGetSymbolAddress((void**)&attn, g_attn);
    cudaGetSymbolAddress((void**)&xr, g_x);
    cudaGetSymbolAddress((void**)&wq, g_wq);
    cudaGetSymbolAddress((void**)&wo, g_wo);
    cudaGetSymbolAddress((void**)&rtab, g_rope);

    static bool attr_set = false;
    if (!attr_set) {
        cudaFuncSetAttribute(gemm_mma,
                             cudaFuncAttributeMaxDynamicSharedMemorySize, GEMM_SMEM_BYTES);
        cudaFuncSetAttribute(attn_mma,
                             cudaFuncAttributeMaxDynamicSharedMemorySize, ATTN_SMEM_BYTES);
        attr_set = true;
    }

    // 0) Fused prologue: rope table + tf32 rounding of x, w_qkv, w_out
    {
        int total = N4X + N4Q + N4O;
        prologue_kernel<<<(total + 255) / 256, 256>>>(x, xr, w_qkv, wq, w_out, wo, rtab);
    }

    // 1) QKV projection with fused RoPE + k,v tf32 rounding
    {
        dim3 grid(QKVN_ / 128, NTOK_ / 128);
        gemm_mma<<<grid, 256, GEMM_SMEM_BYTES>>>(xr, wq, nullptr, qkv, QKVN_, rtab, 1);
    }

    // 2) Attention (BQ=128, R12 config)
    {
        dim3 grid(SEQ_ / 128, BT_ * NH_);
        attn_mma<<<grid, 128, ATTN_SMEM_BYTES>>>(qkv, attn);
    }

    // 3) Output projection + bias
    {
        dim3 grid(INNER_ / 128, NTOK_ / 128);
        gemm_mma<<<grid, 256, GEMM_SMEM_BYTES>>>(attn, wo, b_out, out, INNER_, nullptr, 0);
    }
}